// round 16
// baseline (speedup 1.0000x reference)
#include <cuda_runtime.h>
#include <cuda_fp16.h>
#include <cuda_bf16.h>
#include <cstdint>

#define N_NODES 10000
#define D 128
#define CAP 192          // per-node bucket capacity (max degree ~100 for Poisson(64))
#define PAD 64           // counter stride in ints (256 B) -> spreads LTS slices

// Scratch (no allocations allowed -> __device__ globals).
// NOTE: g_cnt relies on zero-init at module load; gather_kernel resets each
// counter to 0 after consuming it, so every launch starts from zero.
__device__ int    g_cnt[N_NODES * PAD];     // 2.56 MB, one counter per 256 B
__device__ int    g_bucket[N_NODES * CAP];  // 7.68 MB (768 B/node -> int4 aligned)
__device__ __half g_xh[N_NODES * D];        // 2.5 MB fp16 copy of x
__device__ __half g_h[N_NODES * D];         // 2.5 MB aggregated messages (fp16)
__device__ __half g_wt[D * D];              // 32 KB W transposed [n][k] fp16

// ---------------------------------------------------------------------------
// 1. fused fill + convert, 4 edges per thread (4 independent atomics in
//    flight -> hides ATOMG latency). Convert is fully vectorized.
//    Grid: ceil(E/4 / 256) = 625 blocks for E=640000.
// ---------------------------------------------------------------------------
__global__ void fill_convert_kernel(const int* __restrict__ src,
                                    const int* __restrict__ dst,
                                    const float* __restrict__ x,
                                    const float* __restrict__ W,
                                    int n_edges) {
    int t = blockIdx.x * blockDim.x + threadIdx.x;

    // ---- fill: edges [4t, 4t+3] ----
    int base = t * 4;
    if (base + 3 < n_edges) {
        int4 d4 = *(const int4*)&dst[base];
        int4 s4 = *(const int4*)&src[base];
        int sl0 = atomicAdd(&g_cnt[d4.x * PAD], 1);
        int sl1 = atomicAdd(&g_cnt[d4.y * PAD], 1);
        int sl2 = atomicAdd(&g_cnt[d4.z * PAD], 1);
        int sl3 = atomicAdd(&g_cnt[d4.w * PAD], 1);
        if (sl0 < CAP) g_bucket[d4.x * CAP + sl0] = s4.x;
        if (sl1 < CAP) g_bucket[d4.y * CAP + sl1] = s4.y;
        if (sl2 < CAP) g_bucket[d4.z * CAP + sl2] = s4.z;
        if (sl3 < CAP) g_bucket[d4.w * CAP + sl3] = s4.w;
    } else {
        for (int e = base; e < n_edges; e++) {
            int d = dst[e];
            int slot = atomicAdd(&g_cnt[d * PAD], 1);
            if (slot < CAP) g_bucket[d * CAP + slot] = src[e];
        }
    }

    // ---- convert x -> fp16: thread t handles 8 floats (2 float4 -> 1 uint4).
    //      160000 threads x 8 = 1.28M floats = all of x. ----
    if (t < N_NODES * D / 8) {
        const float4* xin = (const float4*)(x + t * 8);
        float4 va = xin[0];
        float4 vb = xin[1];
        __half2 h0 = __floats2half2_rn(va.x, va.y);
        __half2 h1 = __floats2half2_rn(va.z, va.w);
        __half2 h2 = __floats2half2_rn(vb.x, vb.y);
        __half2 h3 = __floats2half2_rn(vb.z, vb.w);
        uint4 pk;
        pk.x = *(unsigned int*)&h0;
        pk.y = *(unsigned int*)&h1;
        pk.z = *(unsigned int*)&h2;
        pk.w = *(unsigned int*)&h3;
        ((uint4*)g_xh)[t] = pk;
    }

    // ---- convert W -> fp16 transposed ----
    if (t < D * D) {               // W[k][n] -> g_wt[n][k]
        int k = t >> 7, n = t & 127;
        g_wt[n * D + k] = __float2half_rn(W[t]);
    }
}

// ---------------------------------------------------------------------------
// 2. gather-side reduction: one warp per node, fp16 reads, fp32 accumulate.
//    Unroll-4 (MLP=4). Lane 0 resets the node's counter for the next replay.
// ---------------------------------------------------------------------------
__global__ void gather_kernel() {
    int node = blockIdx.x * 8 + (threadIdx.x >> 5);
    int lane = threadIdx.x & 31;
    if (node >= N_NODES) return;

    int n = g_cnt[node * PAD];
    if (lane == 0) g_cnt[node * PAD] = 0;    // reset for next graph replay
    if (n > CAP) n = CAP;
    const int* bk = g_bucket + node * CAP;   // 768B-aligned -> int4 ok

    float a00 = 0.f, a01 = 0.f, a02 = 0.f, a03 = 0.f;
    float a10 = 0.f, a11 = 0.f, a12 = 0.f, a13 = 0.f;
    float a20 = 0.f, a21 = 0.f, a22 = 0.f, a23 = 0.f;
    float a30 = 0.f, a31 = 0.f, a32 = 0.f, a33 = 0.f;

    int e = 0;
    for (; e + 3 < n; e += 4) {
        int4 s4 = *(const int4*)&bk[e];
        uint2 p0 = ((const uint2*)(g_xh + (size_t)s4.x * D))[lane];
        uint2 p1 = ((const uint2*)(g_xh + (size_t)s4.y * D))[lane];
        uint2 p2 = ((const uint2*)(g_xh + (size_t)s4.z * D))[lane];
        uint2 p3 = ((const uint2*)(g_xh + (size_t)s4.w * D))[lane];
        float2 f0a = __half22float2(*(const __half2*)&p0.x);
        float2 f0b = __half22float2(*(const __half2*)&p0.y);
        float2 f1a = __half22float2(*(const __half2*)&p1.x);
        float2 f1b = __half22float2(*(const __half2*)&p1.y);
        float2 f2a = __half22float2(*(const __half2*)&p2.x);
        float2 f2b = __half22float2(*(const __half2*)&p2.y);
        float2 f3a = __half22float2(*(const __half2*)&p3.x);
        float2 f3b = __half22float2(*(const __half2*)&p3.y);
        a00 += f0a.x; a01 += f0a.y; a02 += f0b.x; a03 += f0b.y;
        a10 += f1a.x; a11 += f1a.y; a12 += f1b.x; a13 += f1b.y;
        a20 += f2a.x; a21 += f2a.y; a22 += f2b.x; a23 += f2b.y;
        a30 += f3a.x; a31 += f3a.y; a32 += f3b.x; a33 += f3b.y;
    }
    for (; e < n; e++) {
        int s0 = bk[e];
        uint2 p0 = ((const uint2*)(g_xh + (size_t)s0 * D))[lane];
        float2 f0 = __half22float2(*(const __half2*)&p0.x);
        float2 f1 = __half22float2(*(const __half2*)&p0.y);
        a00 += f0.x; a01 += f0.y; a02 += f1.x; a03 += f1.y;
    }

    float r0 = (a00 + a10) + (a20 + a30);
    float r1 = (a01 + a11) + (a21 + a31);
    float r2 = (a02 + a12) + (a22 + a32);
    float r3 = (a03 + a13) + (a23 + a33);

    __half2 h0 = __floats2half2_rn(r0, r1);
    __half2 h1 = __floats2half2_rn(r2, r3);
    uint2 pk;
    pk.x = *(unsigned int*)&h0;
    pk.y = *(unsigned int*)&h1;
    ((uint2*)(g_h + (size_t)node * D))[lane] = pk;
}

// ---------------------------------------------------------------------------
// 3. out = relu(h @ W + b), fp16 mma.m16n8k16, fp32 accum.
//    Block 512 thr (16 warps) = 128 rows x 128 cols -> grid 79, ONE wave.
//    Warp tile 32 rows x 32 cols = 2 m-tiles x 4 n-tiles.
//    Whole Wt + h tile in dynamic smem (69.6 KB); one sync; unrolled.
//    Staging check: 512 thr x 64 B (4 x uint4) = 32 KB = full 128x128 fp16 tile.
//    Strides 136 halves -> frag-load banks (4*gid+tig)%32 all distinct.
// ---------------------------------------------------------------------------
#define ROWS_PER_BLK 128
#define GEMM_THREADS 512
#define HS2 136    // halves per hs row
#define WS2 136    // halves per ws n-row
#define GEMM_SMEM_BYTES ((ROWS_PER_BLK * HS2 + D * WS2) * 2)

__device__ __forceinline__ void mma_f16(float* c, const unsigned int* a,
                                        unsigned int b0, unsigned int b1) {
    asm volatile(
        "mma.sync.aligned.m16n8k16.row.col.f32.f16.f16.f32 "
        "{%0,%1,%2,%3}, {%4,%5,%6,%7}, {%8,%9}, {%0,%1,%2,%3};"
        : "+f"(c[0]), "+f"(c[1]), "+f"(c[2]), "+f"(c[3])
        : "r"(a[0]), "r"(a[1]), "r"(a[2]), "r"(a[3]), "r"(b0), "r"(b1));
}

__global__ void gemm_tc_kernel(const float* __restrict__ b,
                               float* __restrict__ out) {
    extern __shared__ __half smem_pool[];
    __half* hs = smem_pool;                       // [128][HS2]
    __half* ws = smem_pool + ROWS_PER_BLK * HS2;  // [128][WS2] (W transposed)

    int tid   = threadIdx.x;
    int warp  = tid >> 5;
    int lane  = tid & 31;
    int mwarp = warp & 3;    // rows mwarp*32
    int nwarp = warp >> 2;   // cols nwarp*32
    int gid   = lane >> 2;   // 0..7
    int tig   = lane & 3;    // 0..3
    int row0  = blockIdx.x * ROWS_PER_BLK;

    // ---- stage h tile: thread t -> row t>>2 (128 rows), 32-half seg (t&3).
    //      32 halves = 64 B = 4 x uint4 per thread. ----
    {
        int r   = tid >> 2;
        int seg = (tid & 3) * 32;
        int grow = row0 + r;
        uint4 v[4] = {make_uint4(0,0,0,0), make_uint4(0,0,0,0),
                      make_uint4(0,0,0,0), make_uint4(0,0,0,0)};
        if (grow < N_NODES) {
            const uint4* src = (const uint4*)(g_h + (size_t)grow * D + seg);
#pragma unroll
            for (int j = 0; j < 4; j++) v[j] = src[j];
        }
        uint4* dst4 = (uint4*)&hs[r * HS2 + seg];
#pragma unroll
        for (int j = 0; j < 4; j++) dst4[j] = v[j];
    }
    // ---- stage whole Wt: thread t -> n-row t>>2, 32-half segment (t&3).
    //      Also 4 x uint4 per thread. ----
    {
        int n   = tid >> 2;
        int seg = (tid & 3) * 32;
        const uint4* src = (const uint4*)(g_wt + n * D + seg);
        uint4* dst4 = (uint4*)&ws[n * WS2 + seg];
#pragma unroll
        for (int j = 0; j < 4; j++) dst4[j] = src[j];
    }
    __syncthreads();

    float acc[2][4][4];
#pragma unroll
    for (int mt = 0; mt < 2; mt++)
#pragma unroll
        for (int nt = 0; nt < 4; nt++)
#pragma unroll
            for (int j = 0; j < 4; j++) acc[mt][nt][j] = 0.f;

#pragma unroll
    for (int ks = 0; ks < 8; ks++) {
        int kb = ks * 16;
        unsigned int a[2][4];
#pragma unroll
        for (int mt = 0; mt < 2; mt++) {
            int r = mwarp * 32 + mt * 16;
            a[mt][0] = *(const unsigned int*)&hs[(r + gid)     * HS2 + kb + 2 * tig];
            a[mt][1] = *(const unsigned int*)&hs[(r + gid + 8) * HS2 + kb + 2 * tig];
            a[mt][2] = *(const unsigned int*)&hs[(r + gid)     * HS2 + kb + 2 * tig + 8];
            a[mt][3] = *(const unsigned int*)&hs[(r + gid + 8) * HS2 + kb + 2 * tig + 8];
        }
#pragma unroll
        for (int nt = 0; nt < 4; nt++) {
            int c = nwarp * 32 + nt * 8 + gid;
            unsigned int b0 = *(const unsigned int*)&ws[c * WS2 + kb + 2 * tig];
            unsigned int b1 = *(const unsigned int*)&ws[c * WS2 + kb + 2 * tig + 8];
            mma_f16(acc[0][nt], a[0], b0, b1);
            mma_f16(acc[1][nt], a[1], b0, b1);
        }
    }

    // Epilogue: bias + relu; c0/c1 adjacent cols -> float2 stores.
#pragma unroll
    for (int mt = 0; mt < 2; mt++) {
#pragma unroll
        for (int nt = 0; nt < 4; nt++) {
            int r = row0 + mwarp * 32 + mt * 16 + gid;
            int c = nwarp * 32 + nt * 8 + tig * 2;
            float b0 = b[c], b1 = b[c + 1];
            if (r < N_NODES) {
                float2 v = make_float2(fmaxf(acc[mt][nt][0] + b0, 0.f),
                                       fmaxf(acc[mt][nt][1] + b1, 0.f));
                *(float2*)&out[r * D + c] = v;
            }
            if (r + 8 < N_NODES) {
                float2 v = make_float2(fmaxf(acc[mt][nt][2] + b0, 0.f),
                                       fmaxf(acc[mt][nt][3] + b1, 0.f));
                *(float2*)&out[(r + 8) * D + c] = v;
            }
        }
    }
}

// ---------------------------------------------------------------------------
// Launch chain (graph-capturable, default stream). 3 launches.
// Inputs: x [10000,128] f32, src [E] i32, dst [E] i32, W [128,128] f32, b [128] f32.
// ---------------------------------------------------------------------------
extern "C" void kernel_launch(void* const* d_in, const int* in_sizes, int n_in,
                              void* d_out, int out_size) {
    const float* x   = (const float*)d_in[0];
    const int*   src = (const int*)  d_in[1];
    const int*   dst = (const int*)  d_in[2];
    const float* W   = (const float*)d_in[3];
    const float* b   = (const float*)d_in[4];
    float*       out = (float*)d_out;
    int E = in_sizes[1];

    // Host-side attribute set (not a stream op; capture-safe, idempotent).
    cudaFuncSetAttribute(gemm_tc_kernel,
                         cudaFuncAttributeMaxDynamicSharedMemorySize,
                         GEMM_SMEM_BYTES);

    int fill_threads = (E + 3) / 4;                  // 4 edges per thread
    int conv_threads = N_NODES * D / 8;              // 8 floats per thread
    int total_threads = fill_threads > conv_threads ? fill_threads : conv_threads;
    fill_convert_kernel<<<(total_threads + 255) / 256, 256>>>(src, dst, x, W, E);
    gather_kernel<<<(N_NODES + 7) / 8, 256>>>();
    gemm_tc_kernel<<<(N_NODES + ROWS_PER_BLK - 1) / ROWS_PER_BLK, GEMM_THREADS,
                     GEMM_SMEM_BYTES>>>(b, out);
}